// round 12
// baseline (speedup 1.0000x reference)
#include <cuda_runtime.h>
#include <cuda_bf16.h>
#include <cstdint>

#define ND_MAX 50000
#define NE_MAX 640000
#define DD 128
#define BM 128
#define GEMM_THREADS 256

// SMEM layout (bytes). Rows padded to 136 bf16 = 272B (conflict-free frags)
#define ROWB 272
#define SM_BIAS  0
#define SM_AHI   512
#define SM_ALO   (SM_AHI + 128*ROWB)
#define SM_WHI   (SM_ALO + 128*ROWB)
#define SM_WLO   (SM_WHI + 128*ROWB)
#define SM_TOTAL (SM_WLO + 128*ROWB)  // 139,776 B

// ---- scratch (no allocation allowed; static device globals) ----
__device__ float g_agg[ND_MAX * DD];
__device__ float g_buf0[ND_MAX * DD];
__device__ float g_buf1[ND_MAX * DD];
__device__ int   g_cnt_out[ND_MAX];
__device__ int   g_cnt_in[ND_MAX];
__device__ int   g_start[ND_MAX];
__device__ int   g_fill[ND_MAX];
__device__ int   g_total;
__device__ int2  g_csr[NE_MAX];       // packed {src, bitcast(inv_out[src])}
__device__ float g_inv_out[ND_MAX];
__device__ float g_inv_in[ND_MAX];
// W^T bf16 images per layer: [L][hi 32KB | lo 32KB], WT[n*128+k]
__device__ __align__(16) unsigned char g_Wc[3 * 65536];

// ---------------- setup kernels (4 launches total) ----------------
__global__ void zero_setup_kernel(int n) {
    int i = blockIdx.x * blockDim.x + threadIdx.x;
    if (i < n) { g_cnt_out[i] = 0; g_cnt_in[i] = 0; g_fill[i] = 0; }
    if (i == 0) g_total = 0;
}

// 4 edges per thread, front-batched loads + independent atomics
__global__ void count_kernel(const int* __restrict__ src, const int* __restrict__ dst, int e) {
    int base = (blockIdx.x * blockDim.x + threadIdx.x) * 4;
    if (base + 4 <= e) {
        int s0 = __ldg(&src[base + 0]), s1 = __ldg(&src[base + 1]);
        int s2 = __ldg(&src[base + 2]), s3 = __ldg(&src[base + 3]);
        int d0 = __ldg(&dst[base + 0]), d1 = __ldg(&dst[base + 1]);
        int d2 = __ldg(&dst[base + 2]), d3 = __ldg(&dst[base + 3]);
        atomicAdd(&g_cnt_out[s0], 1); atomicAdd(&g_cnt_out[s1], 1);
        atomicAdd(&g_cnt_out[s2], 1); atomicAdd(&g_cnt_out[s3], 1);
        atomicAdd(&g_cnt_in[d0], 1);  atomicAdd(&g_cnt_in[d1], 1);
        atomicAdd(&g_cnt_in[d2], 1);  atomicAdd(&g_cnt_in[d3], 1);
    } else {
        for (int i = base; i < e; i++) {
            atomicAdd(&g_cnt_out[__ldg(&src[i])], 1);
            atomicAdd(&g_cnt_in[__ldg(&dst[i])], 1);
        }
    }
}

// CSR range allocation via atomic cursor (row ranges need not be ordered) + inv
__global__ void alloc_inv_kernel(int n) {
    int i = blockIdx.x * blockDim.x + threadIdx.x;
    if (i < n) {
        int c = g_cnt_in[i];
        g_start[i] = atomicAdd(&g_total, c);
        g_inv_out[i] = rsqrtf((float)max(g_cnt_out[i], 1));
        g_inv_in[i]  = rsqrtf((float)max(c, 1));
    }
}

// fill (4 edges/thread, packed entries) + wconv fused
__global__ void fill_wconv_kernel(const int* __restrict__ src, const int* __restrict__ dst,
                                  int e, const float* __restrict__ Ws, int wtot) {
    int tidg = blockIdx.x * blockDim.x + threadIdx.x;
    int base = tidg * 4;
    if (base + 4 <= e) {
        int s0 = __ldg(&src[base + 0]), s1 = __ldg(&src[base + 1]);
        int s2 = __ldg(&src[base + 2]), s3 = __ldg(&src[base + 3]);
        int d0 = __ldg(&dst[base + 0]), d1 = __ldg(&dst[base + 1]);
        int d2 = __ldg(&dst[base + 2]), d3 = __ldg(&dst[base + 3]);
        float i0 = __ldg(&g_inv_out[s0]), i1 = __ldg(&g_inv_out[s1]);
        float i2 = __ldg(&g_inv_out[s2]), i3 = __ldg(&g_inv_out[s3]);
        int p0 = atomicAdd(&g_fill[d0], 1);
        int p1 = atomicAdd(&g_fill[d1], 1);
        int p2 = atomicAdd(&g_fill[d2], 1);
        int p3 = atomicAdd(&g_fill[d3], 1);
        g_csr[__ldg(&g_start[d0]) + p0] = make_int2(s0, __float_as_int(i0));
        g_csr[__ldg(&g_start[d1]) + p1] = make_int2(s1, __float_as_int(i1));
        g_csr[__ldg(&g_start[d2]) + p2] = make_int2(s2, __float_as_int(i2));
        g_csr[__ldg(&g_start[d3]) + p3] = make_int2(s3, __float_as_int(i3));
    } else {
        for (int i = base; i < e; i++) {
            int s = __ldg(&src[i]);
            int d = __ldg(&dst[i]);
            int pos = __ldg(&g_start[d]) + atomicAdd(&g_fill[d], 1);
            g_csr[pos] = make_int2(s, __float_as_int(__ldg(&g_inv_out[s])));
        }
    }
    if (tidg < wtot) {
        int l = tidg / (DD * DD);
        int r = tidg % (DD * DD);
        int k = r / DD, nn = r % DD;
        float w = Ws[tidg];
        __nv_bfloat16 hi = __float2bfloat16_rn(w);
        __nv_bfloat16 lo = __float2bfloat16_rn(w - __bfloat162float(hi));
        unsigned char* bptr = g_Wc + (size_t)l * 65536;
        *reinterpret_cast<__nv_bfloat16*>(bptr + (nn * DD + k) * 2) = hi;
        *reinterpret_cast<__nv_bfloat16*>(bptr + 32768 + (nn * DD + k) * 2) = lo;
    }
}

// ---------------- gather: one warp per dst node, packed csr (2-deep chain) ----------------
__global__ void gather_kernel(const float* __restrict__ x, int n) {
    int gid  = blockIdx.x * blockDim.x + threadIdx.x;
    int node = gid >> 5;
    if (node >= n) return;
    int lane = gid & 31;

    const int2* csr = g_csr;
    int start = g_start[node];
    int end   = start + g_cnt_in[node];

    float4 accA = make_float4(0.f, 0.f, 0.f, 0.f);
    float4 accB = make_float4(0.f, 0.f, 0.f, 0.f);

    int j = start;
    for (; j + 4 <= end; j += 4) {
        int2 p0 = __ldg(&csr[j + 0]);
        int2 p1 = __ldg(&csr[j + 1]);
        int2 p2 = __ldg(&csr[j + 2]);
        int2 p3 = __ldg(&csr[j + 3]);
        float4 v0 = __ldg(reinterpret_cast<const float4*>(x + (size_t)p0.x * DD) + lane);
        float4 v1 = __ldg(reinterpret_cast<const float4*>(x + (size_t)p1.x * DD) + lane);
        float4 v2 = __ldg(reinterpret_cast<const float4*>(x + (size_t)p2.x * DD) + lane);
        float4 v3 = __ldg(reinterpret_cast<const float4*>(x + (size_t)p3.x * DD) + lane);
        float c0 = __int_as_float(p0.y), c1 = __int_as_float(p1.y);
        float c2 = __int_as_float(p2.y), c3 = __int_as_float(p3.y);
        accA.x += v0.x * c0; accA.y += v0.y * c0; accA.z += v0.z * c0; accA.w += v0.w * c0;
        accB.x += v1.x * c1; accB.y += v1.y * c1; accB.z += v1.z * c1; accB.w += v1.w * c1;
        accA.x += v2.x * c2; accA.y += v2.y * c2; accA.z += v2.z * c2; accA.w += v2.w * c2;
        accB.x += v3.x * c3; accB.y += v3.y * c3; accB.z += v3.z * c3; accB.w += v3.w * c3;
    }
    if (j + 2 <= end) {
        int2 p0 = __ldg(&csr[j + 0]);
        int2 p1 = __ldg(&csr[j + 1]);
        float4 v0 = __ldg(reinterpret_cast<const float4*>(x + (size_t)p0.x * DD) + lane);
        float4 v1 = __ldg(reinterpret_cast<const float4*>(x + (size_t)p1.x * DD) + lane);
        float c0 = __int_as_float(p0.y), c1 = __int_as_float(p1.y);
        accA.x += v0.x * c0; accA.y += v0.y * c0; accA.z += v0.z * c0; accA.w += v0.w * c0;
        accB.x += v1.x * c1; accB.y += v1.y * c1; accB.z += v1.z * c1; accB.w += v1.w * c1;
        j += 2;
    }
    if (j < end) {
        int2 p0 = __ldg(&csr[j]);
        float4 v0 = __ldg(reinterpret_cast<const float4*>(x + (size_t)p0.x * DD) + lane);
        float c0 = __int_as_float(p0.y);
        accA.x += v0.x * c0; accA.y += v0.y * c0; accA.z += v0.z * c0; accA.w += v0.w * c0;
    }

    float si = g_inv_in[node];
    float4 acc;
    acc.x = (accA.x + accB.x) * si;
    acc.y = (accA.y + accB.y) * si;
    acc.z = (accA.z + accB.z) * si;
    acc.w = (accA.w + accB.w) * si;
    reinterpret_cast<float4*>(g_agg + (size_t)node * DD)[lane] = acc;
}

// ---------------- mma.sync bf16x3 GEMM: out = relu(g_agg @ W + b) ----------------
__device__ __forceinline__ void mma16816(float* c, const uint32_t* a, uint32_t b0, uint32_t b1) {
    asm volatile(
        "mma.sync.aligned.m16n8k16.row.col.f32.bf16.bf16.f32 "
        "{%0,%1,%2,%3}, {%4,%5,%6,%7}, {%8,%9}, {%0,%1,%2,%3};"
        : "+f"(c[0]), "+f"(c[1]), "+f"(c[2]), "+f"(c[3])
        : "r"(a[0]), "r"(a[1]), "r"(a[2]), "r"(a[3]), "r"(b0), "r"(b1));
}

__global__ void __launch_bounds__(GEMM_THREADS, 1)
gemm_tc_kernel(const unsigned char* __restrict__ Wc,   // W^T hi|lo (64KB)
               const float* __restrict__ bias,
               float* __restrict__ out, int n) {
    extern __shared__ char smem[];
    int tid = threadIdx.x;
    int wid = tid >> 5;
    int lane = tid & 31;
    int qp = lane & 3;
    int qr = lane >> 2;
    int wr = wid & 3;
    int wc = wid >> 2;
    int r0 = blockIdx.x * BM;

    if (tid < DD) reinterpret_cast<float*>(smem + SM_BIAS)[tid] = bias[tid];

    {
        const uint32_t* whi = reinterpret_cast<const uint32_t*>(Wc);
        const uint32_t* wlo = reinterpret_cast<const uint32_t*>(Wc + 32768);
        #pragma unroll
        for (int i = tid; i < DD * (DD / 2); i += GEMM_THREADS) {
            int nn = i >> 6;
            int kw = i & 63;
            *reinterpret_cast<uint32_t*>(smem + SM_WHI + nn * ROWB + kw * 4) = whi[i];
            *reinterpret_cast<uint32_t*>(smem + SM_WLO + nn * ROWB + kw * 4) = wlo[i];
        }
    }

    {
        #pragma unroll
        for (int q = tid; q < DD * BM / 4; q += GEMM_THREADS) {
            int row = q >> 5;
            int col = (q & 31) << 2;
            int gr = r0 + row;
            float4 v = make_float4(0.f, 0.f, 0.f, 0.f);
            if (gr < n) v = __ldg(reinterpret_cast<const float4*>(g_agg + (size_t)gr * DD + col));
            __nv_bfloat16 h0 = __float2bfloat16_rn(v.x);
            __nv_bfloat16 h1 = __float2bfloat16_rn(v.y);
            __nv_bfloat16 h2 = __float2bfloat16_rn(v.z);
            __nv_bfloat16 h3 = __float2bfloat16_rn(v.w);
            __nv_bfloat16 l0 = __float2bfloat16_rn(v.x - __bfloat162float(h0));
            __nv_bfloat16 l1 = __float2bfloat16_rn(v.y - __bfloat162float(h1));
            __nv_bfloat16 l2 = __float2bfloat16_rn(v.z - __bfloat162float(h2));
            __nv_bfloat16 l3 = __float2bfloat16_rn(v.w - __bfloat162float(h3));
            uint2 hp, lp;
            hp.x = (uint32_t)__bfloat16_as_ushort(h0) | ((uint32_t)__bfloat16_as_ushort(h1) << 16);
            hp.y = (uint32_t)__bfloat16_as_ushort(h2) | ((uint32_t)__bfloat16_as_ushort(h3) << 16);
            lp.x = (uint32_t)__bfloat16_as_ushort(l0) | ((uint32_t)__bfloat16_as_ushort(l1) << 16);
            lp.y = (uint32_t)__bfloat16_as_ushort(l2) | ((uint32_t)__bfloat16_as_ushort(l3) << 16);
            *reinterpret_cast<uint2*>(smem + SM_AHI + row * ROWB + col * 2) = hp;
            *reinterpret_cast<uint2*>(smem + SM_ALO + row * ROWB + col * 2) = lp;
        }
    }
    __syncthreads();

    float acc[2][8][4];
    #pragma unroll
    for (int m = 0; m < 2; m++)
        #pragma unroll
        for (int t = 0; t < 8; t++)
            #pragma unroll
            for (int i = 0; i < 4; i++) acc[m][t][i] = 0.f;

    #pragma unroll
    for (int ks = 0; ks < 8; ks++) {
        uint32_t ah[2][4], al[2][4];
        #pragma unroll
        for (int m = 0; m < 2; m++) {
            int arow = wr * 32 + m * 16 + qr;
            int ab = arow * ROWB + ks * 32 + qp * 4;
            ah[m][0] = *reinterpret_cast<const uint32_t*>(smem + SM_AHI + ab);
            ah[m][1] = *reinterpret_cast<const uint32_t*>(smem + SM_AHI + ab + 8 * ROWB);
            ah[m][2] = *reinterpret_cast<const uint32_t*>(smem + SM_AHI + ab + 16);
            ah[m][3] = *reinterpret_cast<const uint32_t*>(smem + SM_AHI + ab + 8 * ROWB + 16);
            al[m][0] = *reinterpret_cast<const uint32_t*>(smem + SM_ALO + ab);
            al[m][1] = *reinterpret_cast<const uint32_t*>(smem + SM_ALO + ab + 8 * ROWB);
            al[m][2] = *reinterpret_cast<const uint32_t*>(smem + SM_ALO + ab + 16);
            al[m][3] = *reinterpret_cast<const uint32_t*>(smem + SM_ALO + ab + 8 * ROWB + 16);
        }
        #pragma unroll
        for (int nt = 0; nt < 8; nt++) {
            int ncol = wc * 64 + nt * 8 + qr;
            int bb = ncol * ROWB + ks * 32 + qp * 4;
            uint32_t bh0 = *reinterpret_cast<const uint32_t*>(smem + SM_WHI + bb);
            uint32_t bh1 = *reinterpret_cast<const uint32_t*>(smem + SM_WHI + bb + 16);
            uint32_t bl0 = *reinterpret_cast<const uint32_t*>(smem + SM_WLO + bb);
            uint32_t bl1 = *reinterpret_cast<const uint32_t*>(smem + SM_WLO + bb + 16);
            #pragma unroll
            for (int m = 0; m < 2; m++) {
                mma16816(acc[m][nt], ah[m], bh0, bh1);
                mma16816(acc[m][nt], ah[m], bl0, bl1);
                mma16816(acc[m][nt], al[m], bh0, bh1);
            }
        }
    }

    const float* bsm = reinterpret_cast<const float*>(smem + SM_BIAS);
    #pragma unroll
    for (int m = 0; m < 2; m++) {
        int row  = r0 + wr * 32 + m * 16 + qr;
        int row2 = row + 8;
        #pragma unroll
        for (int nt = 0; nt < 8; nt++) {
            int col = wc * 64 + nt * 8 + qp * 2;
            float bx = bsm[col], by = bsm[col + 1];
            if (row < n) {
                float2 o;
                o.x = fmaxf(acc[m][nt][0] + bx, 0.f);
                o.y = fmaxf(acc[m][nt][1] + by, 0.f);
                *reinterpret_cast<float2*>(out + (size_t)row * DD + col) = o;
            }
            if (row2 < n) {
                float2 o;
                o.x = fmaxf(acc[m][nt][2] + bx, 0.f);
                o.y = fmaxf(acc[m][nt][3] + by, 0.f);
                *reinterpret_cast<float2*>(out + (size_t)row2 * DD + col) = o;
            }
        }
    }
}

// ---------------------------------------------------------------
extern "C" void kernel_launch(void* const* d_in, const int* in_sizes, int n_in,
                              void* d_out, int out_size) {
    const float* x   = (const float*)d_in[0];
    const float* Ws  = (const float*)d_in[1];
    const float* bs  = (const float*)d_in[2];
    const int*   src = (const int*)d_in[3];
    const int*   dst = (const int*)d_in[4];
    float* out = (float*)d_out;

    int n = in_sizes[0] / DD;
    int e = in_sizes[3];
    int L = in_sizes[1] / (DD * DD);

    float *buf0, *buf1;
    cudaGetSymbolAddress((void**)&buf0, g_buf0);
    cudaGetSymbolAddress((void**)&buf1, g_buf1);
    unsigned char* wc;
    cudaGetSymbolAddress((void**)&wc, g_Wc);

    cudaFuncSetAttribute(gemm_tc_kernel,
                         cudaFuncAttributeMaxDynamicSharedMemorySize, SM_TOTAL);

    int nbN = (n + 255) / 256;
    int wtot = L * DD * DD;
    int e4 = (e + 3) / 4;                       // threads for 4-edge batching
    int nbE4 = (e4 + 255) / 256;
    // fill_wconv grid must also cover wtot threads (wconv uses thread id directly)
    int fillThreads = (e4 > wtot) ? e4 : wtot;
    int nbFill = (fillThreads + 255) / 256;

    // ---- CSR build + degrees + W conversion: 4 launches
    zero_setup_kernel<<<nbN, 256>>>(n);
    count_kernel<<<nbE4, 256>>>(src, dst, e);
    alloc_inv_kernel<<<nbN, 256>>>(n);
    fill_wconv_kernel<<<nbFill, 256>>>(src, dst, e, Ws, wtot);

    long gth = (long)n * 32;
    int gather_blocks = (int)((gth + 255) / 256);
    int gemm_blocks = (n + BM - 1) / BM;

    const float* cur = x;
    for (int l = 0; l < L; l++) {
        gather_kernel<<<gather_blocks, 256>>>(cur, n);
        float* o = (l == L - 1) ? out : ((l & 1) == 0 ? buf0 : buf1);
        gemm_tc_kernel<<<gemm_blocks, GEMM_THREADS, SM_TOTAL>>>(
            wc + (size_t)l * 65536, bs + (size_t)l * DD, o, n);
        cur = o;
    }
}

// round 13
// speedup vs baseline: 1.0588x; 1.0588x over previous
#include <cuda_runtime.h>
#include <cuda_bf16.h>
#include <cstdint>

#define ND_MAX 50000
#define NE_MAX 640000
#define DD 128
#define BM 128
#define GEMM_THREADS 256

// SMEM layout (bytes). Rows padded to 136 bf16 = 272B (conflict-free frags)
#define ROWB 272
#define SM_BIAS  0
#define SM_AHI   512
#define SM_ALO   (SM_AHI + 128*ROWB)
#define SM_WHI   (SM_ALO + 128*ROWB)
#define SM_WLO   (SM_WHI + 128*ROWB)
#define SM_TOTAL (SM_WLO + 128*ROWB)  // 139,776 B

// ---- scratch (no allocation allowed; static device globals) ----
__device__ float g_agg[ND_MAX * DD];
__device__ float g_buf0[ND_MAX * DD];
__device__ float g_buf1[ND_MAX * DD];
__device__ int   g_cnt_out[ND_MAX];
__device__ int   g_cnt_in[ND_MAX];
__device__ int   g_start[ND_MAX];
__device__ int   g_eslot[NE_MAX];     // per-edge slot within its dst row
__device__ int   g_total;
__device__ int   g_csr_src[NE_MAX];
__device__ float g_inv_out[ND_MAX];
__device__ float g_inv_in[ND_MAX];
// W^T bf16 images per layer: [L][hi 32KB | lo 32KB], WT[n*128+k]
__device__ __align__(16) unsigned char g_Wc[3 * 65536];

// ---------------- setup kernels (4 launches total) ----------------
__global__ void zero_setup_kernel(int n) {
    int i = blockIdx.x * blockDim.x + threadIdx.x;
    if (i < n) { g_cnt_out[i] = 0; g_cnt_in[i] = 0; }
    if (i == 0) g_total = 0;
}

// count degrees; the cnt_in atomic's return value IS the edge's CSR slot
__global__ void count_kernel(const int* __restrict__ src, const int* __restrict__ dst, int e) {
    int i = blockIdx.x * blockDim.x + threadIdx.x;
    if (i < e) {
        atomicAdd(&g_cnt_out[__ldg(&src[i])], 1);
        g_eslot[i] = atomicAdd(&g_cnt_in[__ldg(&dst[i])], 1);
    }
}

// CSR range allocation via atomic cursor + inv + W bf16 hi/lo conversion
__global__ void alloc_inv_wconv_kernel(int n, const float* __restrict__ Ws, int wtot) {
    int i = blockIdx.x * blockDim.x + threadIdx.x;
    if (i < n) {
        int c = g_cnt_in[i];
        g_start[i] = atomicAdd(&g_total, c);
        g_inv_out[i] = rsqrtf((float)max(g_cnt_out[i], 1));
        g_inv_in[i]  = rsqrtf((float)max(c, 1));
    }
    if (i < wtot) {
        int l = i / (DD * DD);
        int r = i % (DD * DD);
        int k = r / DD, nn = r % DD;
        float w = Ws[i];
        __nv_bfloat16 hi = __float2bfloat16_rn(w);
        __nv_bfloat16 lo = __float2bfloat16_rn(w - __bfloat162float(hi));
        unsigned char* base = g_Wc + (size_t)l * 65536;
        *reinterpret_cast<__nv_bfloat16*>(base + (nn * DD + k) * 2) = hi;
        *reinterpret_cast<__nv_bfloat16*>(base + 32768 + (nn * DD + k) * 2) = lo;
    }
}

// fill: NO atomics — slot was recorded by count
__global__ void fill_kernel(const int* __restrict__ src, const int* __restrict__ dst, int e) {
    int i = blockIdx.x * blockDim.x + threadIdx.x;
    if (i < e) {
        int d = __ldg(&dst[i]);
        int pos = __ldg(&g_start[d]) + __ldg(&g_eslot[i]);
        g_csr_src[pos] = __ldg(&src[i]);
    }
}

// ---------------- gather: one warp per dst node (proven R11 version) ----------------
__global__ void gather_kernel(const float* __restrict__ x, int n) {
    int gid  = blockIdx.x * blockDim.x + threadIdx.x;
    int node = gid >> 5;
    if (node >= n) return;
    int lane = gid & 31;

    const int* csr = g_csr_src;
    int start = g_start[node];
    int cnt   = g_cnt_in[node];
    int end   = start + cnt;

    float4 accA = make_float4(0.f, 0.f, 0.f, 0.f);
    float4 accB = make_float4(0.f, 0.f, 0.f, 0.f);

    int j = start;
    for (; j + 4 <= end; j += 4) {
        int s0 = __ldg(&csr[j + 0]);
        int s1 = __ldg(&csr[j + 1]);
        int s2 = __ldg(&csr[j + 2]);
        int s3 = __ldg(&csr[j + 3]);
        float c0 = __ldg(&g_inv_out[s0]);
        float c1 = __ldg(&g_inv_out[s1]);
        float c2 = __ldg(&g_inv_out[s2]);
        float c3 = __ldg(&g_inv_out[s3]);
        float4 v0 = __ldg(reinterpret_cast<const float4*>(x + (size_t)s0 * DD) + lane);
        float4 v1 = __ldg(reinterpret_cast<const float4*>(x + (size_t)s1 * DD) + lane);
        float4 v2 = __ldg(reinterpret_cast<const float4*>(x + (size_t)s2 * DD) + lane);
        float4 v3 = __ldg(reinterpret_cast<const float4*>(x + (size_t)s3 * DD) + lane);
        accA.x += v0.x * c0; accA.y += v0.y * c0; accA.z += v0.z * c0; accA.w += v0.w * c0;
        accB.x += v1.x * c1; accB.y += v1.y * c1; accB.z += v1.z * c1; accB.w += v1.w * c1;
        accA.x += v2.x * c2; accA.y += v2.y * c2; accA.z += v2.z * c2; accA.w += v2.w * c2;
        accB.x += v3.x * c3; accB.y += v3.y * c3; accB.z += v3.z * c3; accB.w += v3.w * c3;
    }
    if (j + 2 <= end) {
        int s0 = __ldg(&csr[j + 0]);
        int s1 = __ldg(&csr[j + 1]);
        float c0 = __ldg(&g_inv_out[s0]);
        float c1 = __ldg(&g_inv_out[s1]);
        float4 v0 = __ldg(reinterpret_cast<const float4*>(x + (size_t)s0 * DD) + lane);
        float4 v1 = __ldg(reinterpret_cast<const float4*>(x + (size_t)s1 * DD) + lane);
        accA.x += v0.x * c0; accA.y += v0.y * c0; accA.z += v0.z * c0; accA.w += v0.w * c0;
        accB.x += v1.x * c1; accB.y += v1.y * c1; accB.z += v1.z * c1; accB.w += v1.w * c1;
        j += 2;
    }
    if (j < end) {
        int s0 = __ldg(&csr[j]);
        float c0 = __ldg(&g_inv_out[s0]);
        float4 v0 = __ldg(reinterpret_cast<const float4*>(x + (size_t)s0 * DD) + lane);
        accA.x += v0.x * c0; accA.y += v0.y * c0; accA.z += v0.z * c0; accA.w += v0.w * c0;
    }

    float si = g_inv_in[node];
    float4 acc;
    acc.x = (accA.x + accB.x) * si;
    acc.y = (accA.y + accB.y) * si;
    acc.z = (accA.z + accB.z) * si;
    acc.w = (accA.w + accB.w) * si;
    reinterpret_cast<float4*>(g_agg + (size_t)node * DD)[lane] = acc;
}

// ---------------- mma.sync bf16x3 GEMM: out = relu(g_agg @ W + b) ----------------
__device__ __forceinline__ void mma16816(float* c, const uint32_t* a, uint32_t b0, uint32_t b1) {
    asm volatile(
        "mma.sync.aligned.m16n8k16.row.col.f32.bf16.bf16.f32 "
        "{%0,%1,%2,%3}, {%4,%5,%6,%7}, {%8,%9}, {%0,%1,%2,%3};"
        : "+f"(c[0]), "+f"(c[1]), "+f"(c[2]), "+f"(c[3])
        : "r"(a[0]), "r"(a[1]), "r"(a[2]), "r"(a[3]), "r"(b0), "r"(b1));
}

__global__ void __launch_bounds__(GEMM_THREADS, 1)
gemm_tc_kernel(const unsigned char* __restrict__ Wc,   // W^T hi|lo (64KB)
               const float* __restrict__ bias,
               float* __restrict__ out, int n) {
    extern __shared__ char smem[];
    int tid = threadIdx.x;
    int wid = tid >> 5;
    int lane = tid & 31;
    int qp = lane & 3;
    int qr = lane >> 2;
    int wr = wid & 3;
    int wc = wid >> 2;
    int r0 = blockIdx.x * BM;

    if (tid < DD) reinterpret_cast<float*>(smem + SM_BIAS)[tid] = bias[tid];

    {
        const uint32_t* whi = reinterpret_cast<const uint32_t*>(Wc);
        const uint32_t* wlo = reinterpret_cast<const uint32_t*>(Wc + 32768);
        #pragma unroll
        for (int i = tid; i < DD * (DD / 2); i += GEMM_THREADS) {
            int nn = i >> 6;
            int kw = i & 63;
            *reinterpret_cast<uint32_t*>(smem + SM_WHI + nn * ROWB + kw * 4) = whi[i];
            *reinterpret_cast<uint32_t*>(smem + SM_WLO + nn * ROWB + kw * 4) = wlo[i];
        }
    }

    {
        #pragma unroll
        for (int q = tid; q < DD * BM / 4; q += GEMM_THREADS) {
            int row = q >> 5;
            int col = (q & 31) << 2;
            int gr = r0 + row;
            float4 v = make_float4(0.f, 0.f, 0.f, 0.f);
            if (gr < n) v = __ldg(reinterpret_cast<const float4*>(g_agg + (size_t)gr * DD + col));
            __nv_bfloat16 h0 = __float2bfloat16_rn(v.x);
            __nv_bfloat16 h1 = __float2bfloat16_rn(v.y);
            __nv_bfloat16 h2 = __float2bfloat16_rn(v.z);
            __nv_bfloat16 h3 = __float2bfloat16_rn(v.w);
            __nv_bfloat16 l0 = __float2bfloat16_rn(v.x - __bfloat162float(h0));
            __nv_bfloat16 l1 = __float2bfloat16_rn(v.y - __bfloat162float(h1));
            __nv_bfloat16 l2 = __float2bfloat16_rn(v.z - __bfloat162float(h2));
            __nv_bfloat16 l3 = __float2bfloat16_rn(v.w - __bfloat162float(h3));
            uint2 hp, lp;
            hp.x = (uint32_t)__bfloat16_as_ushort(h0) | ((uint32_t)__bfloat16_as_ushort(h1) << 16);
            hp.y = (uint32_t)__bfloat16_as_ushort(h2) | ((uint32_t)__bfloat16_as_ushort(h3) << 16);
            lp.x = (uint32_t)__bfloat16_as_ushort(l0) | ((uint32_t)__bfloat16_as_ushort(l1) << 16);
            lp.y = (uint32_t)__bfloat16_as_ushort(l2) | ((uint32_t)__bfloat16_as_ushort(l3) << 16);
            *reinterpret_cast<uint2*>(smem + SM_AHI + row * ROWB + col * 2) = hp;
            *reinterpret_cast<uint2*>(smem + SM_ALO + row * ROWB + col * 2) = lp;
        }
    }
    __syncthreads();

    float acc[2][8][4];
    #pragma unroll
    for (int m = 0; m < 2; m++)
        #pragma unroll
        for (int t = 0; t < 8; t++)
            #pragma unroll
            for (int i = 0; i < 4; i++) acc[m][t][i] = 0.f;

    #pragma unroll
    for (int ks = 0; ks < 8; ks++) {
        uint32_t ah[2][4], al[2][4];
        #pragma unroll
        for (int m = 0; m < 2; m++) {
            int arow = wr * 32 + m * 16 + qr;
            int ab = arow * ROWB + ks * 32 + qp * 4;
            ah[m][0] = *reinterpret_cast<const uint32_t*>(smem + SM_AHI + ab);
            ah[m][1] = *reinterpret_cast<const uint32_t*>(smem + SM_AHI + ab + 8 * ROWB);
            ah[m][2] = *reinterpret_cast<const uint32_t*>(smem + SM_AHI + ab + 16);
            ah[m][3] = *reinterpret_cast<const uint32_t*>(smem + SM_AHI + ab + 8 * ROWB + 16);
            al[m][0] = *reinterpret_cast<const uint32_t*>(smem + SM_ALO + ab);
            al[m][1] = *reinterpret_cast<const uint32_t*>(smem + SM_ALO + ab + 8 * ROWB);
            al[m][2] = *reinterpret_cast<const uint32_t*>(smem + SM_ALO + ab + 16);
            al[m][3] = *reinterpret_cast<const uint32_t*>(smem + SM_ALO + ab + 8 * ROWB + 16);
        }
        #pragma unroll
        for (int nt = 0; nt < 8; nt++) {
            int ncol = wc * 64 + nt * 8 + qr;
            int bb = ncol * ROWB + ks * 32 + qp * 4;
            uint32_t bh0 = *reinterpret_cast<const uint32_t*>(smem + SM_WHI + bb);
            uint32_t bh1 = *reinterpret_cast<const uint32_t*>(smem + SM_WHI + bb + 16);
            uint32_t bl0 = *reinterpret_cast<const uint32_t*>(smem + SM_WLO + bb);
            uint32_t bl1 = *reinterpret_cast<const uint32_t*>(smem + SM_WLO + bb + 16);
            #pragma unroll
            for (int m = 0; m < 2; m++) {
                mma16816(acc[m][nt], ah[m], bh0, bh1);
                mma16816(acc[m][nt], ah[m], bl0, bl1);
                mma16816(acc[m][nt], al[m], bh0, bh1);
            }
        }
    }

    const float* bsm = reinterpret_cast<const float*>(smem + SM_BIAS);
    #pragma unroll
    for (int m = 0; m < 2; m++) {
        int row  = r0 + wr * 32 + m * 16 + qr;
        int row2 = row + 8;
        #pragma unroll
        for (int nt = 0; nt < 8; nt++) {
            int col = wc * 64 + nt * 8 + qp * 2;
            float bx = bsm[col], by = bsm[col + 1];
            if (row < n) {
                float2 o;
                o.x = fmaxf(acc[m][nt][0] + bx, 0.f);
                o.y = fmaxf(acc[m][nt][1] + by, 0.f);
                *reinterpret_cast<float2*>(out + (size_t)row * DD + col) = o;
            }
            if (row2 < n) {
                float2 o;
                o.x = fmaxf(acc[m][nt][2] + bx, 0.f);
                o.y = fmaxf(acc[m][nt][3] + by, 0.f);
                *reinterpret_cast<float2*>(out + (size_t)row2 * DD + col) = o;
            }
        }
    }
}

// ---------------------------------------------------------------
extern "C" void kernel_launch(void* const* d_in, const int* in_sizes, int n_in,
                              void* d_out, int out_size) {
    const float* x   = (const float*)d_in[0];
    const float* Ws  = (const float*)d_in[1];
    const float* bs  = (const float*)d_in[2];
    const int*   src = (const int*)d_in[3];
    const int*   dst = (const int*)d_in[4];
    float* out = (float*)d_out;

    int n = in_sizes[0] / DD;
    int e = in_sizes[3];
    int L = in_sizes[1] / (DD * DD);

    float *buf0, *buf1;
    cudaGetSymbolAddress((void**)&buf0, g_buf0);
    cudaGetSymbolAddress((void**)&buf1, g_buf1);
    unsigned char* wc;
    cudaGetSymbolAddress((void**)&wc, g_Wc);

    cudaFuncSetAttribute(gemm_tc_kernel,
                         cudaFuncAttributeMaxDynamicSharedMemorySize, SM_TOTAL);

    int nbN = (n + 255) / 256;
    int nbE = (e + 255) / 256;
    int wtot = L * DD * DD;
    int allocThreads = (n > wtot) ? n : wtot;
    int nbAlloc = (allocThreads + 255) / 256;

    // ---- CSR build + degrees + W conversion: 4 launches
    zero_setup_kernel<<<nbN, 256>>>(n);
    count_kernel<<<nbE, 256>>>(src, dst, e);
    alloc_inv_wconv_kernel<<<nbAlloc, 256>>>(n, Ws, wtot);
    fill_kernel<<<nbE, 256>>>(src, dst, e);

    long gth = (long)n * 32;
    int gather_blocks = (int)((gth + 255) / 256);
    int gemm_blocks = (n + BM - 1) / BM;

    const float* cur = x;
    for (int l = 0; l < L; l++) {
        gather_kernel<<<gather_blocks, 256>>>(cur, n);
        float* o = (l == L - 1) ? out : ((l & 1) == 0 ? buf0 : buf1);
        gemm_tc_kernel<<<gemm_blocks, GEMM_THREADS, SM_TOTAL>>>(
            wc + (size_t)l * 65536, bs + (size_t)l * DD, o, n);
        cur = o;
    }
}